// round 13
// baseline (speedup 1.0000x reference)
#include <cuda_runtime.h>
#include <cuda_bf16.h>
#include <mma.h>
#include <cstddef>
#include <cstdint>
using namespace nvcuda;

#define Bsz 256
#define Lsz 2048
#define BL  (Bsz*Lsz)   // 524288 tokens

// ---------------- scratch ----------------
__device__ float g_Hf[(size_t)BL * 64];   // forward prestates [BL][64]
__device__ float g_Hb[(size_t)BL * 64];   // backward prestates
__device__ float g_T[4 * 64 * 64];
__device__ float g_gateW[68 * 256];       // folded gate weights [k][256]; cols: zf|htf|zb|htb
__device__ float g_gateB[256];
__device__ float g_headW[192 * 128];      // folded head weights [k][128]
__device__ float g_headB[128];
__device__ float g_bp[64];                // sorted breakpoints
__device__ int   g_rank[64];
__device__ float2 g_gateC[65 * 256];      // per-segment (c0,c1) gate PWL table
__device__ float2 g_headC[65 * 128];      // per-segment (c0,c1) head PWL table
__device__ __nv_bfloat16 g_headWh[128 * 128];  // head W hi/lo, [k][128]
__device__ __nv_bfloat16 g_headWl[128 * 128];

__device__ __forceinline__ float htanh(float v) {
    float r;
    asm("tanh.approx.f32 %0, %1;" : "=f"(r) : "f"(v));
    return r;
}

// ---------------- prep: fold weights (parallel) ----------------
__global__ void prepA_kernel(const float* fwz, const float* fbz, const float* fwh, const float* fbh,
                             const float* bwz, const float* bbz, const float* bwh, const float* bbh,
                             const float* fpw, const float* fpb, const float* bpw, const float* bpb)
{
    const int tid = threadIdx.x;
    const int g = tid >> 6, i = tid & 63;
    const int bid = blockIdx.x;
    const float* A  = (g==0) ? fwz : (g==1) ? fwh : (g==2) ? bwz : bwh;
    const float* ab = (g==0) ? fbz : (g==1) ? fbh : (g==2) ? bbz : bbh;
    const float* P  = (g<2) ? fpw : bpw;
    const float* pb = (g<2) ? fpb : bpb;

    if (bid < 64) {
        const int j = bid;
        float s = 0.f;
#pragma unroll 8
        for (int h = 0; h < 64; ++h) s = fmaf(A[i*64+h], P[h*67 + 3 + j], s);
        g_T[(size_t)(g*64+i)*64 + j] = s;
    } else if (bid < 67) {
        const int c = bid - 64;
        float s = 0.f;
#pragma unroll 8
        for (int h = 0; h < 64; ++h) s = fmaf(A[i*64+h], P[h*67 + c], s);
        g_gateW[c*256 + g*64 + i] = s;
    } else {
        float s = ab[i];
#pragma unroll 8
        for (int h = 0; h < 64; ++h) s = fmaf(A[i*64+h], pb[h], s);
        g_gateB[g*64 + i] = s;
        g_gateW[67*256 + tid] = 0.f;
    }
}

__global__ void prepB_kernel(const float* tew2, const float* teb2)
{
    const int o = threadIdx.x;
    const int bid = blockIdx.x;
    const float* T = &g_T[(size_t)o * 64];
    if (bid < 64) {
        const int k = bid;
        float s = 0.f;
#pragma unroll 8
        for (int j = 0; j < 64; ++j) s = fmaf(T[j], tew2[j*64 + k], s);
        g_gateW[(3+k)*256 + o] = s;
    } else {
        float s = 0.f;
#pragma unroll 8
        for (int j = 0; j < 64; ++j) s = fmaf(T[j], teb2[j], s);
        g_gateB[o] += s;
    }
}

__global__ void prepHead_kernel(const float* ghw1, const float* ghb1,
                                const float* tew2, const float* teb2)
{
    const int o = threadIdx.x;
    const int bid = blockIdx.x;
    if (bid < 64) {
        const int k = bid;
        float s = 0.f;
#pragma unroll 8
        for (int j = 0; j < 64; ++j) s = fmaf(ghw1[o*192 + 128 + j], tew2[j*64 + k], s);
        g_headW[(128+k)*128 + o] = s;
    } else if (bid == 64) {
        for (int k = 0; k < 128; ++k) g_headW[k*128 + o] = ghw1[o*192 + k];
    } else {
        float s = ghb1[o];
#pragma unroll 8
        for (int j = 0; j < 64; ++j) s = fmaf(ghw1[o*192 + 128 + j], teb2[j], s);
        g_headB[o] = s;
    }
}

// parallel bf16 hi/lo split of head W rows 0..127  (grid 128 x 128 threads)
__global__ void convHead_kernel()
{
    const int k = blockIdx.x, o = threadIdx.x;
    const float w = g_headW[k*128 + o];
    const __nv_bfloat16 h = __float2bfloat16(w);
    g_headWh[k*128 + o] = h;
    g_headWl[k*128 + o] = __float2bfloat16(w - __bfloat162float(h));
}

// ---------------- PWL table construction ----------------
__global__ void prepBP_kernel(const float* tew1, const float* teb1)
{
    __shared__ float bpv[64];
    const int k = threadIdx.x;
    const float a = tew1[k], b = teb1[k];
    const float v = (a != 0.f) ? (-b / a) : -1e38f;
    bpv[k] = v;
    __syncthreads();
    int r = 0;
    for (int j = 0; j < 64; ++j) {
        float u = bpv[j];
        if (u < v || (u == v && j < k)) ++r;
    }
    g_bp[r] = v;
    g_rank[k] = r;
}

__global__ void prepGateTab_kernel(const float* tew1, const float* teb1)
{
    const int s = blockIdx.x, o = threadIdx.x;
    float c0 = 0.f, c1 = 0.f;
    for (int j = 0; j < 64; ++j) {
        const float a = tew1[j], b = teb1[j];
        const int rj = g_rank[j];
        const bool act = (a == 0.f) ? (b > 0.f) : ((a > 0.f) ? (s > rj) : (s <= rj));
        if (act) {
            const float m = g_gateW[(3+j)*256 + o];
            c0 = fmaf(m, b, c0);
            c1 = fmaf(m, a, c1);
        }
    }
    g_gateC[s*256 + o] = make_float2(c0, c1);
}

__global__ void prepHeadTab_kernel(const float* tew1, const float* teb1)
{
    const int s = blockIdx.x, o = threadIdx.x;
    float c0 = 0.f, c1 = 0.f;
    for (int j = 0; j < 64; ++j) {
        const float a = tew1[j], b = teb1[j];
        const int rj = g_rank[j];
        const bool act = (a == 0.f) ? (b > 0.f) : ((a > 0.f) ? (s > rj) : (s <= rj));
        if (act) {
            const float m = g_headW[(128+j)*128 + o];
            c0 = fmaf(m, b, c0);
            c1 = fmaf(m, a, c1);
        }
    }
    g_headC[s*128 + o] = make_float2(c0, c1);
}

// ---------------- fused gates (PWL) + scan: channel-split, 6 blocks/SM (R12, proven) ----------------
// grid (256, 2, 2) = (batch, dir, channel-half); 256 threads.
#define Z_LD 129
#define FUSED_SMEM (2 * 32 * Z_LD * 4)   // zsm[32][129] + hsm[32][129] = 33024 B

__global__ void __launch_bounds__(256, 6)
fused_kernel(const float* __restrict__ x, const float* __restrict__ tt,
             const float* __restrict__ mtok)
{
    extern __shared__ float sm[];
    float* zsm = sm;                 // [32][129]
    float* hsm = sm + 32*Z_LD;       // [32][129]
    __shared__ float bp[64];
    __shared__ float x0s[128], x1s[128], ms[128], ts[128];
    __shared__ int   segs[128];
    __shared__ float mtk[2];

    const int tid = threadIdx.x;
    const int b   = blockIdx.x;
    const int dir = blockIdx.y;
    const int chb = blockIdx.z;      // channel half: 0 or 1

    if (tid < 64) bp[tid] = g_bp[tid];
    if (tid < 2)  mtk[tid] = mtok[tid];

    const int lane = tid & 31;
    const int wrp  = tid >> 5;       // 0..7
    const int p    = lane & 15;      // pair index
    const int t0   = wrp * 16;       // 16 tokens per warp
    const bool isz = (lane < 16);
    const int obase = dir*128 + (isz ? 0 : 64) + chb*32 + p*2;   // 2 outs per lane
    const int lc = p*2;              // local channel row

    float w0[2], w1[2], w2[2], bb[2];
#pragma unroll
    for (int i = 0; i < 2; ++i) {
        w0[i] = g_gateW[0*256 + obase + i];
        w1[i] = g_gateW[1*256 + obase + i];
        w2[i] = g_gateW[2*256 + obase + i];
        bb[i] = g_gateB[obase + i];
    }
    __syncthreads();

    float* Hout = (dir ? g_Hb : g_Hf) + (size_t)b * Lsz * 64 + chb*32;
    float* dst = isz ? zsm : hsm;
    float hcar = 0.f;

    for (int ci = 0; ci < 16; ++ci) {
        const int c = dir ? (15 - ci) : ci;
        const size_t gb = (size_t)b * Lsz + (size_t)c * 128;

        if (tid < 128) {       // token staging + segment search
            const size_t g = gb + tid;
            float m  = x[g*3 + 2];
            float x0 = x[g*3 + 0];
            float x1 = x[g*3 + 1];
            if (m == 0.f) { x0 = mtk[0]; x1 = mtk[1]; }
            const float tv = tt[g];
            x0s[tid] = x0; x1s[tid] = x1; ms[tid] = m; ts[tid] = tv;
            int s = 0;
#pragma unroll
            for (int st = 32; st; st >>= 1)
                if (bp[s + st - 1] < tv) s += st;
            segs[tid] = s;
        }
        __syncthreads();

#pragma unroll 4
        for (int u = 0; u < 16; ++u) {
            const int tok = t0 + u;
            const int s = segs[tok];
            const float tv = ts[tok], x0 = x0s[tok], x1 = x1s[tok], mv = ms[tok];
            const float4 cc = *(const float4*)&g_gateC[(size_t)s*256 + obase];
            float pre[2];
            pre[0] = fmaf(cc.y, tv, cc.x);
            pre[1] = fmaf(cc.w, tv, cc.z);
#pragma unroll
            for (int i = 0; i < 2; ++i) {
                float v = pre[i] + bb[i];
                v = fmaf(w0[i], x0, v);
                v = fmaf(w1[i], x1, v);
                v = fmaf(w2[i], mv, v);
                if (isz) {
                    v = fmaf(0.5f, htanh(0.5f * v), 0.5f);   // sigmoid via HW tanh
                } else {
                    v = htanh(v);                             // HW tanh
                }
                dst[(lc + i)*Z_LD + tok] = v;
            }
        }
        __syncthreads();

        if (tid < 32) {        // scan this chunk; local channel = tid
            const float* zr = zsm + tid*Z_LD;
            const float* qr = hsm + tid*Z_LD;
            float* ho = Hout + (size_t)c*128*64 + tid;
            float h = hcar;
            if (dir == 0) {
#pragma unroll 4
                for (int t = 0; t < 128; ++t) {
                    ho[(size_t)t*64] = h;
                    h = fmaf(zr[t], qr[t] - h, h);
                }
            } else {
#pragma unroll 4
                for (int t = 127; t >= 0; --t) {
                    ho[(size_t)t*64] = h;
                    h = fmaf(zr[t], qr[t] - h, h);
                }
            }
            hcar = h;
        }
        __syncthreads();
    }
}

// ---------------- head: wmma bf16x3, M=64 tokens/block, 4 blocks/SM ----------------
#define HW_LDA 136
#define HC_LDC 132
#define HEAD_SMEM (2*64*HW_LDA*2)   // Ah+Al = 34816 B; Csm (64*132*4 = 33792 B) reuses it

__global__ void __launch_bounds__(256, 4)
head_kernel(const float* __restrict__ x, const float* __restrict__ tt,
            const float* __restrict__ ghw2, const float* __restrict__ ghb2,
            float* __restrict__ out)
{
    extern __shared__ char smraw[];
    __nv_bfloat16* Ah = (__nv_bfloat16*)smraw;            // [64][136]
    __nv_bfloat16* Al = Ah + 64*HW_LDA;
    float* Csm = (float*)smraw;                            // reuse A region: [64][132]
    __shared__ __align__(16) float hff[64];
    __shared__ __align__(16) float hbf[64];
    __shared__ float ts[64];
    __shared__ int   segs[64];
    __shared__ float w2s[128], bbs[128], bp[64];

    const int tid = threadIdx.x;
    const size_t base = (size_t)blockIdx.x * 64;
    const int b = (int)(base >> 11);      // 64 | 2048

    if (tid < 64) {
        bp[tid]  = g_bp[tid];
        hff[tid] = g_Hf[(((size_t)b << 11) + (Lsz-1))*64 + tid];
        hbf[tid] = g_Hb[((size_t)b << 11)*64 + tid];
    }
    if (tid >= 64 && tid < 192) { w2s[tid-64] = ghw2[tid-64]; bbs[tid-64] = g_headB[tid-64]; }
    __syncthreads();

    {   // build A hi/lo: token r = tid&63, quarter q = tid>>6 covers 32 K-cols
        const int r = tid & 63;
        const int q = tid >> 6;            // 0..3
        const size_t g = base + r;
        const float m = x[g*3 + 2];
        const bool um = m > 0.f;
        if (q == 0) {
            const float tv = tt[g];
            ts[r] = tv;
            int s = 0;
#pragma unroll
            for (int st = 32; st; st >>= 1)
                if (bp[s + st - 1] < tv) s += st;
            segs[r] = s;
        }
        const int hf = q >> 1;             // 0: h_fwd cols, 1: h_bwd cols
        const int c0 = (q & 1) * 32;       // 32-col subrange
        const float* srcg = (hf ? g_Hb : g_Hf) + g*64 + c0;
        const float* fin  = (hf ? hbf : hff) + c0;
        __nv_bfloat16* dh = Ah + r*HW_LDA + hf*64 + c0;
        __nv_bfloat16* dl = Al + r*HW_LDA + hf*64 + c0;
#pragma unroll
        for (int kg = 0; kg < 4; ++kg) {
            float4 v0 = ((const float4*)srcg)[kg*2];
            float4 v1 = ((const float4*)srcg)[kg*2 + 1];
            if (!um) {
                v0 = ((const float4*)fin)[kg*2];
                v1 = ((const float4*)fin)[kg*2 + 1];
            }
            float vv[8] = {v0.x,v0.y,v0.z,v0.w,v1.x,v1.y,v1.z,v1.w};
            union { uint4 qq; __nv_bfloat162 b2[4]; } uh, ul;
#pragma unroll
            for (int j = 0; j < 4; ++j) {
                const float a0 = vv[2*j], a1 = vv[2*j+1];
                const __nv_bfloat16 h0 = __float2bfloat16(a0);
                const __nv_bfloat16 h1 = __float2bfloat16(a1);
                uh.b2[j] = __halves2bfloat162(h0, h1);
                ul.b2[j] = __halves2bfloat162(__float2bfloat16(a0 - __bfloat162float(h0)),
                                              __float2bfloat16(a1 - __bfloat162float(h1)));
            }
            *(uint4*)(dh + kg*8) = uh.qq;
            *(uint4*)(dl + kg*8) = ul.qq;
        }
    }
    __syncthreads();

    // 8 warps: wm = wrp>>2 (2 row tiles of 32), wn = wrp&3 (4 col tiles of 32)
    const int wrp = tid >> 5;
    const int wm = wrp >> 2;
    const int wn = wrp & 3;

    wmma::fragment<wmma::accumulator,16,16,16,float> acc[2][2];
#pragma unroll
    for (int i = 0; i < 2; ++i)
#pragma unroll
        for (int j = 0; j < 2; ++j) wmma::fill_fragment(acc[i][j], 0.f);

#pragma unroll
    for (int ks = 0; ks < 8; ++ks) {
        wmma::fragment<wmma::matrix_a,16,16,16,__nv_bfloat16,wmma::row_major> fah[2], fal[2];
#pragma unroll
        for (int i = 0; i < 2; ++i) {
            wmma::load_matrix_sync(fah[i], Ah + (wm*32 + i*16)*HW_LDA + ks*16, HW_LDA);
            wmma::load_matrix_sync(fal[i], Al + (wm*32 + i*16)*HW_LDA + ks*16, HW_LDA);
        }
#pragma unroll
        for (int j = 0; j < 2; ++j) {
            wmma::fragment<wmma::matrix_b,16,16,16,__nv_bfloat16,wmma::row_major> fbh, fbl;
            wmma::load_matrix_sync(fbh, g_headWh + (ks*16)*128 + wn*32 + j*16, 128);
            wmma::load_matrix_sync(fbl, g_headWl + (ks*16)*128 + wn*32 + j*16, 128);
#pragma unroll
            for (int i = 0; i < 2; ++i) {
                wmma::mma_sync(acc[i][j], fah[i], fbh, acc[i][j]);
                wmma::mma_sync(acc[i][j], fah[i], fbl, acc[i][j]);
                wmma::mma_sync(acc[i][j], fal[i], fbh, acc[i][j]);
            }
        }
    }
    __syncthreads();   // A dead -> Csm
#pragma unroll
    for (int i = 0; i < 2; ++i)
#pragma unroll
        for (int j = 0; j < 2; ++j)
            wmma::store_matrix_sync(Csm + (wm*32 + i*16)*HC_LDC + wn*32 + j*16,
                                    acc[i][j], HC_LDC, wmma::mem_row_major);
    __syncthreads();

    // fused epilogue: 4 threads per token (32 outs each), 2-step shfl reduce
    {
        const int token = tid >> 2;
        const int q     = tid & 3;
        const int sg = segs[token];
        const float tv = ts[token];
        float s = 0.f;
#pragma unroll
        for (int o4 = 0; o4 < 32; o4 += 4) {
            const int o = q*32 + o4;
            float4 c = *(float4*)&Csm[token*HC_LDC + o];
            const float4* cp = (const float4*)&g_headC[(size_t)sg*128 + o];
            const float4 p0 = cp[0], p1 = cp[1];
            s = fmaf(w2s[o+0], fmaxf(c.x + bbs[o+0] + fmaf(p0.y, tv, p0.x), 0.f), s);
            s = fmaf(w2s[o+1], fmaxf(c.y + bbs[o+1] + fmaf(p0.w, tv, p0.z), 0.f), s);
            s = fmaf(w2s[o+2], fmaxf(c.z + bbs[o+2] + fmaf(p1.y, tv, p1.x), 0.f), s);
            s = fmaf(w2s[o+3], fmaxf(c.w + bbs[o+3] + fmaf(p1.w, tv, p1.z), 0.f), s);
        }
        s += __shfl_xor_sync(0xffffffffu, s, 1);
        s += __shfl_xor_sync(0xffffffffu, s, 2);
        if (q == 0) out[base + token] = s + ghb2[0];
    }
}

// ---------------- launch ----------------
extern "C" void kernel_launch(void* const* d_in, const int* in_sizes, int n_in,
                              void* d_out, int out_size)
{
    (void)in_sizes; (void)n_in; (void)out_size;
    const float* x    = (const float*)d_in[0];
    const float* t    = (const float*)d_in[1];
    const float* mtok = (const float*)d_in[2];
    const float* tew1 = (const float*)d_in[3];
    const float* teb1 = (const float*)d_in[4];
    const float* tew2 = (const float*)d_in[5];
    const float* teb2 = (const float*)d_in[6];
    const float* fpw  = (const float*)d_in[7];
    const float* fpb  = (const float*)d_in[8];
    const float* bpw  = (const float*)d_in[9];
    const float* bpb  = (const float*)d_in[10];
    const float* fwz  = (const float*)d_in[11];
    const float* fbz  = (const float*)d_in[12];
    const float* fwh  = (const float*)d_in[13];
    const float* fbh  = (const float*)d_in[14];
    const float* bwz  = (const float*)d_in[15];
    const float* bbz  = (const float*)d_in[16];
    const float* bwh  = (const float*)d_in[17];
    const float* bbh  = (const float*)d_in[18];
    const float* ghw1 = (const float*)d_in[19];
    const float* ghb1 = (const float*)d_in[20];
    const float* ghw2 = (const float*)d_in[21];
    const float* ghb2 = (const float*)d_in[22];
    float* out = (float*)d_out;

    cudaFuncSetAttribute(fused_kernel, cudaFuncAttributeMaxDynamicSharedMemorySize, FUSED_SMEM);
    cudaFuncSetAttribute(head_kernel,  cudaFuncAttributeMaxDynamicSharedMemorySize, HEAD_SMEM);

    prepA_kernel<<<68, 256>>>(fwz, fbz, fwh, fbh, bwz, bbz, bwh, bbh, fpw, fpb, bpw, bpb);
    prepB_kernel<<<65, 256>>>(tew2, teb2);
    prepHead_kernel<<<66, 128>>>(ghw1, ghb1, tew2, teb2);
    convHead_kernel<<<128, 128>>>();
    prepBP_kernel<<<1, 64>>>(tew1, teb1);
    prepGateTab_kernel<<<65, 256>>>(tew1, teb1);
    prepHeadTab_kernel<<<65, 128>>>(tew1, teb1);

    fused_kernel<<<dim3(Bsz, 2, 2), 256, FUSED_SMEM>>>(x, t, mtok);
    head_kernel<<<BL/64, 256, HEAD_SMEM>>>(x, t, ghw2, ghb2, out);
}

// round 14
// speedup vs baseline: 1.2988x; 1.2988x over previous
#include <cuda_runtime.h>
#include <cuda_bf16.h>
#include <mma.h>
#include <cstddef>
#include <cstdint>
using namespace nvcuda;

#define Bsz 256
#define Lsz 2048
#define BL  (Bsz*Lsz)   // 524288 tokens

// ---------------- scratch ----------------
// H stored as packed bf16x2 (hi in low 16 bits, lo-residual in high 16 bits), 4B/element
__device__ unsigned g_Hf[(size_t)BL * 64];
__device__ unsigned g_Hb[(size_t)BL * 64];
__device__ float g_T[4 * 64 * 64];
__device__ float g_gateW[68 * 256];       // folded gate weights [k][256]; cols: zf|htf|zb|htb
__device__ float g_gateB[256];
__device__ float g_headW[192 * 128];      // folded head weights [k][128]
__device__ float g_headB[128];
__device__ float g_bp[64];                // sorted breakpoints
__device__ int   g_rank[64];
__device__ float2 g_gateC[65 * 256];      // per-segment (c0,c1) gate PWL table
__device__ float2 g_headC[65 * 128];      // per-segment (c0,c1) head PWL table
__device__ __nv_bfloat16 g_headWh[128 * 128];  // head W hi/lo, [k][128]
__device__ __nv_bfloat16 g_headWl[128 * 128];

__device__ __forceinline__ float htanh(float v) {
    float r;
    asm("tanh.approx.f32 %0, %1;" : "=f"(r) : "f"(v));
    return r;
}

// ---------------- prep: fold weights (parallel) ----------------
__global__ void prepA_kernel(const float* fwz, const float* fbz, const float* fwh, const float* fbh,
                             const float* bwz, const float* bbz, const float* bwh, const float* bbh,
                             const float* fpw, const float* fpb, const float* bpw, const float* bpb)
{
    const int tid = threadIdx.x;
    const int g = tid >> 6, i = tid & 63;
    const int bid = blockIdx.x;
    const float* A  = (g==0) ? fwz : (g==1) ? fwh : (g==2) ? bwz : bwh;
    const float* ab = (g==0) ? fbz : (g==1) ? fbh : (g==2) ? bbz : bbh;
    const float* P  = (g<2) ? fpw : bpw;
    const float* pb = (g<2) ? fpb : bpb;

    if (bid < 64) {
        const int j = bid;
        float s = 0.f;
#pragma unroll 8
        for (int h = 0; h < 64; ++h) s = fmaf(A[i*64+h], P[h*67 + 3 + j], s);
        g_T[(size_t)(g*64+i)*64 + j] = s;
    } else if (bid < 67) {
        const int c = bid - 64;
        float s = 0.f;
#pragma unroll 8
        for (int h = 0; h < 64; ++h) s = fmaf(A[i*64+h], P[h*67 + c], s);
        g_gateW[c*256 + g*64 + i] = s;
    } else {
        float s = ab[i];
#pragma unroll 8
        for (int h = 0; h < 64; ++h) s = fmaf(A[i*64+h], pb[h], s);
        g_gateB[g*64 + i] = s;
        g_gateW[67*256 + tid] = 0.f;
    }
}

__global__ void prepB_kernel(const float* tew2, const float* teb2)
{
    const int o = threadIdx.x;
    const int bid = blockIdx.x;
    const float* T = &g_T[(size_t)o * 64];
    if (bid < 64) {
        const int k = bid;
        float s = 0.f;
#pragma unroll 8
        for (int j = 0; j < 64; ++j) s = fmaf(T[j], tew2[j*64 + k], s);
        g_gateW[(3+k)*256 + o] = s;
    } else {
        float s = 0.f;
#pragma unroll 8
        for (int j = 0; j < 64; ++j) s = fmaf(T[j], teb2[j], s);
        g_gateB[o] += s;
    }
}

__global__ void prepHead_kernel(const float* ghw1, const float* ghb1,
                                const float* tew2, const float* teb2)
{
    const int o = threadIdx.x;
    const int bid = blockIdx.x;
    if (bid < 64) {
        const int k = bid;
        float s = 0.f;
#pragma unroll 8
        for (int j = 0; j < 64; ++j) s = fmaf(ghw1[o*192 + 128 + j], tew2[j*64 + k], s);
        g_headW[(128+k)*128 + o] = s;
    } else if (bid == 64) {
        for (int k = 0; k < 128; ++k) g_headW[k*128 + o] = ghw1[o*192 + k];
    } else {
        float s = ghb1[o];
#pragma unroll 8
        for (int j = 0; j < 64; ++j) s = fmaf(ghw1[o*192 + 128 + j], teb2[j], s);
        g_headB[o] = s;
    }
}

// parallel bf16 hi/lo split of head W rows 0..127  (grid 128 x 128 threads)
__global__ void convHead_kernel()
{
    const int k = blockIdx.x, o = threadIdx.x;
    const float w = g_headW[k*128 + o];
    const __nv_bfloat16 h = __float2bfloat16(w);
    g_headWh[k*128 + o] = h;
    g_headWl[k*128 + o] = __float2bfloat16(w - __bfloat162float(h));
}

// ---------------- PWL table construction ----------------
__global__ void prepBP_kernel(const float* tew1, const float* teb1)
{
    __shared__ float bpv[64];
    const int k = threadIdx.x;
    const float a = tew1[k], b = teb1[k];
    const float v = (a != 0.f) ? (-b / a) : -1e38f;
    bpv[k] = v;
    __syncthreads();
    int r = 0;
    for (int j = 0; j < 64; ++j) {
        float u = bpv[j];
        if (u < v || (u == v && j < k)) ++r;
    }
    g_bp[r] = v;
    g_rank[k] = r;
}

// merged gate + head table build: grid 65, block 384 (0-255 gate, 256-383 head)
__global__ void prepTabs_kernel(const float* tew1, const float* teb1)
{
    const int s = blockIdx.x;
    const int tid = threadIdx.x;
    if (tid < 256) {
        const int o = tid;
        float c0 = 0.f, c1 = 0.f;
        for (int j = 0; j < 64; ++j) {
            const float a = tew1[j], b = teb1[j];
            const int rj = g_rank[j];
            const bool act = (a == 0.f) ? (b > 0.f) : ((a > 0.f) ? (s > rj) : (s <= rj));
            if (act) {
                const float m = g_gateW[(3+j)*256 + o];
                c0 = fmaf(m, b, c0);
                c1 = fmaf(m, a, c1);
            }
        }
        g_gateC[s*256 + o] = make_float2(c0, c1);
    } else {
        const int o = tid - 256;
        float c0 = 0.f, c1 = 0.f;
        for (int j = 0; j < 64; ++j) {
            const float a = tew1[j], b = teb1[j];
            const int rj = g_rank[j];
            const bool act = (a == 0.f) ? (b > 0.f) : ((a > 0.f) ? (s > rj) : (s <= rj));
            if (act) {
                const float m = g_headW[(128+j)*128 + o];
                c0 = fmaf(m, b, c0);
                c1 = fmaf(m, a, c1);
            }
        }
        g_headC[s*128 + o] = make_float2(c0, c1);
    }
}

// ---------------- fused gates (PWL) + scan: channel-split, 6 blocks/SM ----------------
// grid (256, 2, 2) = (batch, dir, channel-half); 256 threads.
#define Z_LD 129
#define FUSED_SMEM (2 * 32 * Z_LD * 4)   // zsm[32][129] + hsm[32][129] = 33024 B

__global__ void __launch_bounds__(256, 6)
fused_kernel(const float* __restrict__ x, const float* __restrict__ tt,
             const float* __restrict__ mtok)
{
    extern __shared__ float sm[];
    float* zsm = sm;                 // [32][129]
    float* hsm = sm + 32*Z_LD;       // [32][129]
    __shared__ float bp[64];
    __shared__ float x0s[128], x1s[128], ms[128], ts[128];
    __shared__ int   segs[128];
    __shared__ float mtk[2];

    const int tid = threadIdx.x;
    const int b   = blockIdx.x;
    const int dir = blockIdx.y;
    const int chb = blockIdx.z;      // channel half: 0 or 1

    if (tid < 64) bp[tid] = g_bp[tid];
    if (tid < 2)  mtk[tid] = mtok[tid];

    const int lane = tid & 31;
    const int wrp  = tid >> 5;       // 0..7
    const int p    = lane & 15;      // pair index
    const int t0   = wrp * 16;       // 16 tokens per warp
    const bool isz = (lane < 16);
    const int obase = dir*128 + (isz ? 0 : 64) + chb*32 + p*2;   // 2 outs per lane
    const int lc = p*2;              // local channel row

    float w0[2], w1[2], w2[2], bb[2];
#pragma unroll
    for (int i = 0; i < 2; ++i) {
        w0[i] = g_gateW[0*256 + obase + i];
        w1[i] = g_gateW[1*256 + obase + i];
        w2[i] = g_gateW[2*256 + obase + i];
        bb[i] = g_gateB[obase + i];
    }
    __syncthreads();

    unsigned* Hout = (dir ? g_Hb : g_Hf) + (size_t)b * Lsz * 64 + chb*32;
    float* dst = isz ? zsm : hsm;
    float hcar = 0.f;

    for (int ci = 0; ci < 16; ++ci) {
        const int c = dir ? (15 - ci) : ci;
        const size_t gb = (size_t)b * Lsz + (size_t)c * 128;

        if (tid < 128) {       // token staging + segment search
            const size_t g = gb + tid;
            float m  = x[g*3 + 2];
            float x0 = x[g*3 + 0];
            float x1 = x[g*3 + 1];
            if (m == 0.f) { x0 = mtk[0]; x1 = mtk[1]; }
            const float tv = tt[g];
            x0s[tid] = x0; x1s[tid] = x1; ms[tid] = m; ts[tid] = tv;
            int s = 0;
#pragma unroll
            for (int st = 32; st; st >>= 1)
                if (bp[s + st - 1] < tv) s += st;
            segs[tid] = s;
        }
        __syncthreads();

#pragma unroll 4
        for (int u = 0; u < 16; ++u) {
            const int tok = t0 + u;
            const int s = segs[tok];
            const float tv = ts[tok], x0 = x0s[tok], x1 = x1s[tok], mv = ms[tok];
            const float4 cc = *(const float4*)&g_gateC[(size_t)s*256 + obase];
            float pre[2];
            pre[0] = fmaf(cc.y, tv, cc.x);
            pre[1] = fmaf(cc.w, tv, cc.z);
#pragma unroll
            for (int i = 0; i < 2; ++i) {
                float v = pre[i] + bb[i];
                v = fmaf(w0[i], x0, v);
                v = fmaf(w1[i], x1, v);
                v = fmaf(w2[i], mv, v);
                if (isz) {
                    v = fmaf(0.5f, htanh(0.5f * v), 0.5f);   // sigmoid via HW tanh
                } else {
                    v = htanh(v);                             // HW tanh
                }
                dst[(lc + i)*Z_LD + tok] = v;
            }
        }
        __syncthreads();

        if (tid < 32) {        // scan this chunk; local channel = tid
            const float* zr = zsm + tid*Z_LD;
            const float* qr = hsm + tid*Z_LD;
            unsigned* ho = Hout + (size_t)c*128*64 + tid;
            float h = hcar;
            if (dir == 0) {
#pragma unroll 4
                for (int t = 0; t < 128; ++t) {
                    const __nv_bfloat16 hh = __float2bfloat16(h);
                    const __nv_bfloat16 hl = __float2bfloat16(h - __bfloat162float(hh));
                    __nv_bfloat162 pk = __halves2bfloat162(hh, hl);
                    ho[(size_t)t*64] = *reinterpret_cast<unsigned*>(&pk);
                    h = fmaf(zr[t], qr[t] - h, h);
                }
            } else {
#pragma unroll 4
                for (int t = 127; t >= 0; --t) {
                    const __nv_bfloat16 hh = __float2bfloat16(h);
                    const __nv_bfloat16 hl = __float2bfloat16(h - __bfloat162float(hh));
                    __nv_bfloat162 pk = __halves2bfloat162(hh, hl);
                    ho[(size_t)t*64] = *reinterpret_cast<unsigned*>(&pk);
                    h = fmaf(zr[t], qr[t] - h, h);
                }
            }
            hcar = h;
        }
        __syncthreads();
    }
}

// ---------------- head: wmma bf16x3, M=128, 2 blocks/SM, A from packed bf16x2 H ----------------
#define HW_LDA 136
#define HC_LDC 132
#define HEAD_SMEM (2*128*HW_LDA*2)   // Ah+Al = 69632 B; Csm (67584 B) reuses it

__global__ void __launch_bounds__(256, 2)
head_kernel(const float* __restrict__ x, const float* __restrict__ tt,
            const float* __restrict__ ghw2, const float* __restrict__ ghb2,
            float* __restrict__ out)
{
    extern __shared__ char smraw[];
    __nv_bfloat16* Ah = (__nv_bfloat16*)smraw;            // [128][136]
    __nv_bfloat16* Al = Ah + 128*HW_LDA;
    float* Csm = (float*)smraw;                            // reuse A region: [128][132]
    __shared__ uint4 finF[16], finB[16];                   // final states, packed bf16x2
    __shared__ float ts[128];
    __shared__ int   segs[128];
    __shared__ float w2s[128], bbs[128], bp[64];

    const int tid = threadIdx.x;
    const size_t base = (size_t)blockIdx.x * 128;
    const int b = (int)(base >> 11);      // 128 | 2048

    if (tid < 16)       finF[tid]    = ((const uint4*)(g_Hf + (((size_t)b << 11) + (Lsz-1))*64))[tid];
    else if (tid < 32)  finB[tid-16] = ((const uint4*)(g_Hb + ((size_t)b << 11)*64))[tid-16];
    else if (tid < 96)  bp[tid-32]   = g_bp[tid-32];
    else if (tid < 224) { w2s[tid-96] = ghw2[tid-96]; bbs[tid-96] = g_headB[tid-96]; }
    __syncthreads();

    {   // build A hi/lo: token r = tid&127, half hf = tid>>7 covers 64 K-cols — byte_perm unpack
        const int r  = tid & 127;
        const int hf = tid >> 7;
        const size_t g = base + r;
        const float m = x[g*3 + 2];
        const bool um = m > 0.f;
        if (hf == 0) {
            const float tv = tt[g];
            ts[r] = tv;
            int s = 0;
#pragma unroll
            for (int st = 32; st; st >>= 1)
                if (bp[s + st - 1] < tv) s += st;
            segs[r] = s;
        }
        const uint4* srcg = (const uint4*)((hf ? g_Hb : g_Hf) + g*64);
        const uint4* fin  = hf ? finB : finF;
        __nv_bfloat16* dh = Ah + r*HW_LDA + hf*64;
        __nv_bfloat16* dl = Al + r*HW_LDA + hf*64;
#pragma unroll
        for (int kg = 0; kg < 16; ++kg) {
            uint4 v = srcg[kg];
            if (!um) v = fin[kg];
            uint2 ah, al;
            ah.x = __byte_perm(v.x, v.y, 0x5410);
            ah.y = __byte_perm(v.z, v.w, 0x5410);
            al.x = __byte_perm(v.x, v.y, 0x7632);
            al.y = __byte_perm(v.z, v.w, 0x7632);
            *(uint2*)(dh + kg*4) = ah;
            *(uint2*)(dl + kg*4) = al;
        }
    }
    __syncthreads();

    // 8 warps: wm = wrp>>2 (2 row tiles of 64), wn = wrp&3 (4 col tiles of 32)
    const int wrp = tid >> 5;
    const int wm = wrp >> 2;
    const int wn = wrp & 3;

    wmma::fragment<wmma::accumulator,16,16,16,float> acc[4][2];
#pragma unroll
    for (int i = 0; i < 4; ++i)
#pragma unroll
        for (int j = 0; j < 2; ++j) wmma::fill_fragment(acc[i][j], 0.f);

#pragma unroll
    for (int ks = 0; ks < 8; ++ks) {
        wmma::fragment<wmma::matrix_a,16,16,16,__nv_bfloat16,wmma::row_major> fah[4], fal[4];
#pragma unroll
        for (int i = 0; i < 4; ++i) {
            wmma::load_matrix_sync(fah[i], Ah + (wm*64 + i*16)*HW_LDA + ks*16, HW_LDA);
            wmma::load_matrix_sync(fal[i], Al + (wm*64 + i*16)*HW_LDA + ks*16, HW_LDA);
        }
#pragma unroll
        for (int j = 0; j < 2; ++j) {
            wmma::fragment<wmma::matrix_b,16,16,16,__nv_bfloat16,wmma::row_major> fbh, fbl;
            wmma::load_matrix_sync(fbh, g_headWh + (ks*16)*128 + wn*32 + j*16, 128);
            wmma::load_matrix_sync(fbl, g_headWl + (ks*16)*128 + wn*32 + j*16, 128);
#pragma unroll
            for (int i = 0; i < 4; ++i) {
                wmma::mma_sync(acc[i][j], fah[i], fbh, acc[i][j]);
                wmma::mma_sync(acc[i][j], fah[i], fbl, acc[i][j]);
                wmma::mma_sync(acc[i][j], fal[i], fbh, acc[i][j]);
            }
        }
    }
    __syncthreads();   // A dead -> Csm
#pragma unroll
    for (int i = 0; i < 4; ++i)
#pragma unroll
        for (int j = 0; j < 2; ++j)
            wmma::store_matrix_sync(Csm + (wm*64 + i*16)*HC_LDC + wn*32 + j*16,
                                    acc[i][j], HC_LDC, wmma::mem_row_major);
    __syncthreads();

    // fused epilogue: 2 threads per token (64 outs each), shfl-pair reduce
    {
        const int token = tid >> 1;
        const int half  = tid & 1;
        const int sg = segs[token];
        const float tv = ts[token];
        float s = 0.f;
#pragma unroll
        for (int o4 = 0; o4 < 64; o4 += 4) {
            const int o = half*64 + o4;
            float4 c = *(float4*)&Csm[token*HC_LDC + o];
            const float4* cp = (const float4*)&g_headC[(size_t)sg*128 + o];
            const float4 p0 = cp[0], p1 = cp[1];
            s = fmaf(w2s[o+0], fmaxf(c.x + bbs[o+0] + fmaf(p0.y, tv, p0.x), 0.f), s);
            s = fmaf(w2s[o+1], fmaxf(c.y + bbs[o+1] + fmaf(p0.w, tv, p0.z), 0.f), s);
            s = fmaf(w2s[o+2], fmaxf(c.z + bbs[o+2] + fmaf(p1.y, tv, p1.x), 0.f), s);
            s = fmaf(w2s[o+3], fmaxf(c.w + bbs[o+3] + fmaf(p1.w, tv, p1.z), 0.f), s);
        }
        s += __shfl_xor_sync(0xffffffffu, s, 1);
        if (half == 0) out[base + token] = s + ghb2[0];
    }
}

// ---------------- launch ----------------
extern "C" void kernel_launch(void* const* d_in, const int* in_sizes, int n_in,
                              void* d_out, int out_size)
{
    (void)in_sizes; (void)n_in; (void)out_size;
    const float* x    = (const float*)d_in[0];
    const float* t    = (const float*)d_in[1];
    const float* mtok = (const float*)d_in[2];
    const float* tew1 = (const float*)d_in[3];
    const float* teb1 = (const float*)d_in[4];
    const float* tew2 = (const float*)d_in[5];
    const float* teb2 = (const float*)d_in[6];
    const float* fpw  = (const float*)d_in[7];
    const float* fpb  = (const float*)d_in[8];
    const float* bpw  = (const float*)d_in[9];
    const float* bpb  = (const float*)d_in[10];
    const float* fwz  = (const float*)d_in[11];
    const float* fbz  = (const float*)d_in[12];
    const float* fwh  = (const float*)d_in[13];
    const float* fbh  = (const float*)d_in[14];
    const float* bwz  = (const float*)d_in[15];
    const float* bbz  = (const float*)d_in[16];
    const float* bwh  = (const float*)d_in[17];
    const float* bbh  = (const float*)d_in[18];
    const float* ghw1 = (const float*)d_in[19];
    const float* ghb1 = (const float*)d_in[20];
    const float* ghw2 = (const float*)d_in[21];
    const float* ghb2 = (const float*)d_in[22];
    float* out = (float*)d_out;

    cudaFuncSetAttribute(fused_kernel, cudaFuncAttributeMaxDynamicSharedMemorySize, FUSED_SMEM);
    cudaFuncSetAttribute(head_kernel,  cudaFuncAttributeMaxDynamicSharedMemorySize, HEAD_SMEM);

    prepA_kernel<<<68, 256>>>(fwz, fbz, fwh, fbh, bwz, bbz, bwh, bbh, fpw, fpb, bpw, bpb);
    prepB_kernel<<<65, 256>>>(tew2, teb2);
    prepHead_kernel<<<66, 128>>>(ghw1, ghb1, tew2, teb2);
    convHead_kernel<<<128, 128>>>();
    prepBP_kernel<<<1, 64>>>(tew1, teb1);
    prepTabs_kernel<<<65, 384>>>(tew1, teb1);

    fused_kernel<<<dim3(Bsz, 2, 2), 256, FUSED_SMEM>>>(x, t, mtok);
    head_kernel<<<BL/128, 256, HEAD_SMEM>>>(x, t, ghw2, ghb2, out);
}

// round 16
// speedup vs baseline: 1.3127x; 1.0107x over previous
#include <cuda_runtime.h>
#include <cuda_bf16.h>
#include <mma.h>
#include <cstddef>
#include <cstdint>
using namespace nvcuda;

#define Bsz 256
#define Lsz 2048
#define BL  (Bsz*Lsz)   // 524288 tokens

// ---------------- scratch ----------------
__device__ float g_Hf[(size_t)BL * 64];   // forward prestates [BL][64]
__device__ float g_Hb[(size_t)BL * 64];   // backward prestates
__device__ float g_T[4 * 64 * 64];
__device__ float g_gateW[68 * 256];       // folded gate weights [k][256]; cols: zf|htf|zb|htb
__device__ float g_gateB[256];
__device__ float g_headW[192 * 128];      // folded head weights [k][128]
__device__ float g_headB[128];
__device__ float g_headWt[128 * 128];     // head W rows 0..127, tf32-rounded fp32, [k][128]
__device__ float g_bp[64];                // sorted breakpoints
__device__ int   g_rank[64];
__device__ float2 g_gateC[65 * 256];      // per-segment (c0,c1) gate PWL table
__device__ float2 g_headC[65 * 128];      // per-segment (c0,c1) head PWL table

__device__ __forceinline__ float htanh(float v) {
    float r;
    asm("tanh.approx.f32 %0, %1;" : "=f"(r) : "f"(v));
    return r;
}

// ---------------- prep: fold weights (parallel) ----------------
__global__ void prepA_kernel(const float* fwz, const float* fbz, const float* fwh, const float* fbh,
                             const float* bwz, const float* bbz, const float* bwh, const float* bbh,
                             const float* fpw, const float* fpb, const float* bpw, const float* bpb)
{
    const int tid = threadIdx.x;
    const int g = tid >> 6, i = tid & 63;
    const int bid = blockIdx.x;
    const float* A  = (g==0) ? fwz : (g==1) ? fwh : (g==2) ? bwz : bwh;
    const float* ab = (g==0) ? fbz : (g==1) ? fbh : (g==2) ? bbz : bbh;
    const float* P  = (g<2) ? fpw : bpw;
    const float* pb = (g<2) ? fpb : bpb;

    if (bid < 64) {
        const int j = bid;
        float s = 0.f;
#pragma unroll 8
        for (int h = 0; h < 64; ++h) s = fmaf(A[i*64+h], P[h*67 + 3 + j], s);
        g_T[(size_t)(g*64+i)*64 + j] = s;
    } else if (bid < 67) {
        const int c = bid - 64;
        float s = 0.f;
#pragma unroll 8
        for (int h = 0; h < 64; ++h) s = fmaf(A[i*64+h], P[h*67 + c], s);
        g_gateW[c*256 + g*64 + i] = s;
    } else {
        float s = ab[i];
#pragma unroll 8
        for (int h = 0; h < 64; ++h) s = fmaf(A[i*64+h], pb[h], s);
        g_gateB[g*64 + i] = s;
        g_gateW[67*256 + tid] = 0.f;
    }
}

__global__ void prepB_kernel(const float* tew2, const float* teb2)
{
    const int o = threadIdx.x;
    const int bid = blockIdx.x;
    const float* T = &g_T[(size_t)o * 64];
    if (bid < 64) {
        const int k = bid;
        float s = 0.f;
#pragma unroll 8
        for (int j = 0; j < 64; ++j) s = fmaf(T[j], tew2[j*64 + k], s);
        g_gateW[(3+k)*256 + o] = s;
    } else {
        float s = 0.f;
#pragma unroll 8
        for (int j = 0; j < 64; ++j) s = fmaf(T[j], teb2[j], s);
        g_gateB[o] += s;
    }
}

__global__ void prepHead_kernel(const float* ghw1, const float* ghb1,
                                const float* tew2, const float* teb2)
{
    const int o = threadIdx.x;
    const int bid = blockIdx.x;
    if (bid < 64) {
        const int k = bid;
        float s = 0.f;
#pragma unroll 8
        for (int j = 0; j < 64; ++j) s = fmaf(ghw1[o*192 + 128 + j], tew2[j*64 + k], s);
        g_headW[(128+k)*128 + o] = s;
    } else if (bid == 64) {
        for (int k = 0; k < 128; ++k) g_headW[k*128 + o] = ghw1[o*192 + k];
    } else {
        float s = ghb1[o];
#pragma unroll 8
        for (int j = 0; j < 64; ++j) s = fmaf(ghw1[o*192 + 128 + j], teb2[j], s);
        g_headB[o] = s;
    }
}

// tf32-round head W rows 0..127  (grid 128 x 128 threads)
__global__ void convHead_kernel()
{
    const int k = blockIdx.x, o = threadIdx.x;
    g_headWt[k*128 + o] = wmma::__float_to_tf32(g_headW[k*128 + o]);
}

// ---------------- PWL table construction ----------------
__global__ void prepBP_kernel(const float* tew1, const float* teb1)
{
    __shared__ float bpv[64];
    const int k = threadIdx.x;
    const float a = tew1[k], b = teb1[k];
    const float v = (a != 0.f) ? (-b / a) : -1e38f;
    bpv[k] = v;
    __syncthreads();
    int r = 0;
    for (int j = 0; j < 64; ++j) {
        float u = bpv[j];
        if (u < v || (u == v && j < k)) ++r;
    }
    g_bp[r] = v;
    g_rank[k] = r;
}

// merged gate + head table build: grid 65, block 384 (0-255 gate, 256-383 head)
__global__ void prepTabs_kernel(const float* tew1, const float* teb1)
{
    const int s = blockIdx.x;
    const int tid = threadIdx.x;
    if (tid < 256) {
        const int o = tid;
        float c0 = 0.f, c1 = 0.f;
        for (int j = 0; j < 64; ++j) {
            const float a = tew1[j], b = teb1[j];
            const int rj = g_rank[j];
            const bool act = (a == 0.f) ? (b > 0.f) : ((a > 0.f) ? (s > rj) : (s <= rj));
            if (act) {
                const float m = g_gateW[(3+j)*256 + o];
                c0 = fmaf(m, b, c0);
                c1 = fmaf(m, a, c1);
            }
        }
        g_gateC[s*256 + o] = make_float2(c0, c1);
    } else {
        const int o = tid - 256;
        float c0 = 0.f, c1 = 0.f;
        for (int j = 0; j < 64; ++j) {
            const float a = tew1[j], b = teb1[j];
            const int rj = g_rank[j];
            const bool act = (a == 0.f) ? (b > 0.f) : ((a > 0.f) ? (s > rj) : (s <= rj));
            if (act) {
                const float m = g_headW[(128+j)*128 + o];
                c0 = fmaf(m, b, c0);
                c1 = fmaf(m, a, c1);
            }
        }
        g_headC[s*128 + o] = make_float2(c0, c1);
    }
}

// ---------------- fused gates (PWL) + scan: channel-split, 6 blocks/SM (R12, proven) ----------------
// grid (256, 2, 2) = (batch, dir, channel-half); 256 threads.
#define Z_LD 129
#define FUSED_SMEM (2 * 32 * Z_LD * 4)   // zsm[32][129] + hsm[32][129] = 33024 B

__global__ void __launch_bounds__(256, 6)
fused_kernel(const float* __restrict__ x, const float* __restrict__ tt,
             const float* __restrict__ mtok)
{
    extern __shared__ float sm[];
    float* zsm = sm;                 // [32][129]
    float* hsm = sm + 32*Z_LD;       // [32][129]
    __shared__ float bp[64];
    __shared__ float x0s[128], x1s[128], ms[128], ts[128];
    __shared__ int   segs[128];
    __shared__ float mtk[2];

    const int tid = threadIdx.x;
    const int b   = blockIdx.x;
    const int dir = blockIdx.y;
    const int chb = blockIdx.z;      // channel half: 0 or 1

    if (tid < 64) bp[tid] = g_bp[tid];
    if (tid < 2)  mtk[tid] = mtok[tid];

    const int lane = tid & 31;
    const int wrp  = tid >> 5;       // 0..7
    const int p    = lane & 15;      // pair index
    const int t0   = wrp * 16;       // 16 tokens per warp
    const bool isz = (lane < 16);
    const int obase = dir*128 + (isz ? 0 : 64) + chb*32 + p*2;   // 2 outs per lane
    const int lc = p*2;              // local channel row

    float w0[2], w1[2], w2[2], bb[2];
#pragma unroll
    for (int i = 0; i < 2; ++i) {
        w0[i] = g_gateW[0*256 + obase + i];
        w1[i] = g_gateW[1*256 + obase + i];
        w2[i] = g_gateW[2*256 + obase + i];
        bb[i] = g_gateB[obase + i];
    }
    __syncthreads();

    float* Hout = (dir ? g_Hb : g_Hf) + (size_t)b * Lsz * 64 + chb*32;
    float* dst = isz ? zsm : hsm;
    float hcar = 0.f;

    for (int ci = 0; ci < 16; ++ci) {
        const int c = dir ? (15 - ci) : ci;
        const size_t gb = (size_t)b * Lsz + (size_t)c * 128;

        if (tid < 128) {       // token staging + segment search
            const size_t g = gb + tid;
            float m  = x[g*3 + 2];
            float x0 = x[g*3 + 0];
            float x1 = x[g*3 + 1];
            if (m == 0.f) { x0 = mtk[0]; x1 = mtk[1]; }
            const float tv = tt[g];
            x0s[tid] = x0; x1s[tid] = x1; ms[tid] = m; ts[tid] = tv;
            int s = 0;
#pragma unroll
            for (int st = 32; st; st >>= 1)
                if (bp[s + st - 1] < tv) s += st;
            segs[tid] = s;
        }
        __syncthreads();

#pragma unroll 4
        for (int u = 0; u < 16; ++u) {
            const int tok = t0 + u;
            const int s = segs[tok];
            const float tv = ts[tok], x0 = x0s[tok], x1 = x1s[tok], mv = ms[tok];
            const float4 cc = *(const float4*)&g_gateC[(size_t)s*256 + obase];
            float pre[2];
            pre[0] = fmaf(cc.y, tv, cc.x);
            pre[1] = fmaf(cc.w, tv, cc.z);
#pragma unroll
            for (int i = 0; i < 2; ++i) {
                float v = pre[i] + bb[i];
                v = fmaf(w0[i], x0, v);
                v = fmaf(w1[i], x1, v);
                v = fmaf(w2[i], mv, v);
                if (isz) {
                    v = fmaf(0.5f, htanh(0.5f * v), 0.5f);   // sigmoid via HW tanh
                } else {
                    v = htanh(v);                             // HW tanh
                }
                dst[(lc + i)*Z_LD + tok] = v;
            }
        }
        __syncthreads();

        if (tid < 32) {        // scan this chunk; local channel = tid
            const float* zr = zsm + tid*Z_LD;
            const float* qr = hsm + tid*Z_LD;
            float* ho = Hout + (size_t)c*128*64 + tid;
            float h = hcar;
            if (dir == 0) {
#pragma unroll 4
                for (int t = 0; t < 128; ++t) {
                    ho[(size_t)t*64] = h;
                    h = fmaf(zr[t], qr[t] - h, h);
                }
            } else {
#pragma unroll 4
                for (int t = 127; t >= 0; --t) {
                    ho[(size_t)t*64] = h;
                    h = fmaf(zr[t], qr[t] - h, h);
                }
            }
            hcar = h;
        }
        __syncthreads();
    }
}

// ---------------- head: wmma TF32 single-pass, M=128, 2 blocks/SM, W from global ----------------
#define HA_LD 132
#define HEAD_SMEM (128 * HA_LD * 4)   // Asm = 67584 B; Csm reuses it

__global__ void __launch_bounds__(256, 2)
head_kernel(const float* __restrict__ x, const float* __restrict__ tt,
            const float* __restrict__ ghw2, const float* __restrict__ ghb2,
            float* __restrict__ out)
{
    extern __shared__ char smraw[];
    float* Asm = (float*)smraw;           // [128][132] tf32-rounded fp32
    float* Csm = (float*)smraw;           // reuse after MMA: [128][132]
    __shared__ __align__(16) float hff[64];
    __shared__ __align__(16) float hbf[64];
    __shared__ float ts[128];
    __shared__ int   segs[128];
    __shared__ float w2s[128], bbs[128], bp[64];

    const int tid = threadIdx.x;
    const size_t base = (size_t)blockIdx.x * 128;
    const int b = (int)(base >> 11);      // 128 | 2048

    if (tid < 64) {
        bp[tid]  = g_bp[tid];
        hff[tid] = g_Hf[(((size_t)b << 11) + (Lsz-1))*64 + tid];
        hbf[tid] = g_Hb[((size_t)b << 11)*64 + tid];
    }
    if (tid >= 64 && tid < 192) { w2s[tid-64] = ghw2[tid-64]; bbs[tid-64] = g_headB[tid-64]; }
    __syncthreads();

    {   // build A: token r = tid&127, half hf = tid>>7 covers 64 K-cols; tf32 rounding
        const int r  = tid & 127;
        const int hf = tid >> 7;
        const size_t g = base + r;
        const float m = x[g*3 + 2];
        const bool um = m > 0.f;
        if (hf == 0) {
            const float tv = tt[g];
            ts[r] = tv;
            int s = 0;
#pragma unroll
            for (int st = 32; st; st >>= 1)
                if (bp[s + st - 1] < tv) s += st;
            segs[r] = s;
        }
        const float* srcg = (hf ? g_Hb : g_Hf) + g*64;
        const float* fin  = hf ? hbf : hff;
        float* da = Asm + r*HA_LD + hf*64;
#pragma unroll
        for (int kg = 0; kg < 16; ++kg) {
            float4 v = ((const float4*)srcg)[kg];
            if (!um) v = ((const float4*)fin)[kg];
            v.x = wmma::__float_to_tf32(v.x);
            v.y = wmma::__float_to_tf32(v.y);
            v.z = wmma::__float_to_tf32(v.z);
            v.w = wmma::__float_to_tf32(v.w);
            *(float4*)(da + kg*4) = v;
        }
    }
    __syncthreads();

    // 8 warps: wm = wrp>>2 (2 row tiles of 64), wn = wrp&3 (4 col tiles of 32)
    const int wrp = tid >> 5;
    const int wm = wrp >> 2;
    const int wn = wrp & 3;

    wmma::fragment<wmma::accumulator,16,16,8,float> acc[4][2];
#pragma unroll
    for (int i = 0; i < 4; ++i)
#pragma unroll
        for (int j = 0; j < 2; ++j) wmma::fill_fragment(acc[i][j], 0.f);

#pragma unroll
    for (int ks = 0; ks < 16; ++ks) {
        wmma::fragment<wmma::matrix_a,16,16,8,wmma::precision::tf32,wmma::row_major> fa[4];
#pragma unroll
        for (int i = 0; i < 4; ++i)
            wmma::load_matrix_sync(fa[i], Asm + (wm*64 + i*16)*HA_LD + ks*8, HA_LD);
#pragma unroll
        for (int j = 0; j < 2; ++j) {
            wmma::fragment<wmma::matrix_b,16,16,8,wmma::precision::tf32,wmma::row_major> fb;
            wmma::load_matrix_sync(fb, g_headWt + (ks*8)*128 + wn*32 + j*16, 128);
#pragma unroll
            for (int i = 0; i < 4; ++i)
                wmma::mma_sync(acc[i][j], fa[i], fb, acc[i][j]);
        }
    }
    __syncthreads();   // A dead -> Csm
#pragma unroll
    for (int i = 0; i < 4; ++i)
#pragma unroll
        for (int j = 0; j < 2; ++j)
            wmma::store_matrix_sync(Csm + (wm*64 + i*16)*HA_LD + wn*32 + j*16,
                                    acc[i][j], HA_LD, wmma::mem_row_major);
    __syncthreads();

    // fused epilogue: 2 threads per token (64 outs each), shfl-pair reduce
    {
        const int token = tid >> 1;
        const int half  = tid & 1;
        const int sg = segs[token];
        const float tv = ts[token];
        float s = 0.f;
#pragma unroll
        for (int o4 = 0; o4 < 64; o4 += 4) {
            const int o = half*64 + o4;
            float4 c = *(float4*)&Csm[token*HA_LD + o];
            const float4* cp = (const float4*)&g_headC[(size_t)sg*128 + o];
            const float4 p0 = cp[0], p1 = cp[1];
            s = fmaf(w2s[o+0], fmaxf(c.x + bbs[o+0] + fmaf(p0.y, tv, p0.x), 0.f), s);
            s = fmaf(w2s[o+1], fmaxf(c.y + bbs[o+1] + fmaf(p0.w, tv, p0.z), 0.f), s);
            s = fmaf(w2s[o+2], fmaxf(c.z + bbs[o+2] + fmaf(p1.y, tv, p1.x), 0.f), s);
            s = fmaf(w2s[o+3], fmaxf(c.w + bbs[o+3] + fmaf(p1.w, tv, p1.z), 0.f), s);
        }
        s += __shfl_xor_sync(0xffffffffu, s, 1);
        if (half == 0) out[base + token] = s + ghb2[0];
    }
}

// ---------------- launch ----------------
extern "C" void kernel_launch(void* const* d_in, const int* in_sizes, int n_in,
                              void* d_out, int out_size)
{
    (void)in_sizes; (void)n_in; (void)out_size;
    const float* x    = (const float*)d_in[0];
    const float* t    = (const float*)d_in[1];
    const float* mtok = (const float*)d_in[2];
    const float* tew1 = (const float*)d_in[3];
    const float* teb1 = (const float*)d_in[4];
    const float* tew2 = (const float*)d_in[5];
    const float* teb2 = (const float*)d_in[6];
    const float* fpw  = (const float*)d_in[7];
    const float* fpb  = (const float*)d_in[8];
    const float* bpw  = (const float*)d_in[9];
    const float* bpb  = (const float*)d_in[10];
    const float* fwz  = (const float*)d_in[11];
    const float* fbz  = (const float*)d_in[12];
    const float* fwh  = (const float*)d_in[13];
    const float* fbh  = (const float*)d_in[14];
    const float* bwz  = (const float*)d_in[15];
    const float* bbz  = (const float*)d_in[16];
    const float* bwh  = (const float*)d_in[17];
    const float* bbh  = (const float*)d_in[18];
    const float* ghw1 = (const float*)d_in[19];
    const float* ghb1 = (const float*)d_in[20];
    const float* ghw2 = (const float*)d_in[21];
    const float* ghb2 = (const float*)d_in[22];
    float* out = (float*)d_out;

    cudaFuncSetAttribute(fused_kernel, cudaFuncAttributeMaxDynamicSharedMemorySize, FUSED_SMEM);
    cudaFuncSetAttribute(head_kernel,  cudaFuncAttributeMaxDynamicSharedMemorySize, HEAD_SMEM);

    prepA_kernel<<<68, 256>>>(fwz, fbz, fwh, fbh, bwz, bbz, bwh, bbh, fpw, fpb, bpw, bpb);
    prepB_kernel<<<65, 256>>>(tew2, teb2);
    prepHead_kernel<<<66, 128>>>(ghw1, ghb1, tew2, teb2);
    convHead_kernel<<<128, 128>>>();
    prepBP_kernel<<<1, 64>>>(tew1, teb1);
    prepTabs_kernel<<<65, 384>>>(tew1, teb1);

    fused_kernel<<<dim3(Bsz, 2, 2), 256, FUSED_SMEM>>>(x, t, mtok);
    head_kernel<<<BL/128, 256, HEAD_SMEM>>>(x, t, ghw2, ghb2, out);
}